// round 13
// baseline (speedup 1.0000x reference)
#include <cuda_runtime.h>
#include <cuda_fp16.h>
#include <stdint.h>

#define NB    16
#define N_TOT 16384
#define PPT   128
#define FEAT  256
#define EMB   100
#define OUTW  200

typedef unsigned long long u64;
typedef unsigned int u32;

#define LO_SCALE 2048.0f
#define LO_INV   4.8828125e-4f

// ---------------- mma / ldmatrix (portable ISA) ----------------
__device__ __forceinline__ void mma_f16(float* c,
                                        u32 a0, u32 a1, u32 a2, u32 a3,
                                        u32 b0, u32 b1) {
    asm("mma.sync.aligned.m16n8k16.row.col.f32.f16.f16.f32 "
        "{%0,%1,%2,%3}, {%4,%5,%6,%7}, {%8,%9}, {%0,%1,%2,%3};"
        : "+f"(c[0]), "+f"(c[1]), "+f"(c[2]), "+f"(c[3])
        : "r"(a0), "r"(a1), "r"(a2), "r"(a3), "r"(b0), "r"(b1));
}
__device__ __forceinline__ void ldsm_x4(u32& r0, u32& r1, u32& r2, u32& r3, u32 saddr) {
    asm volatile("ldmatrix.sync.aligned.m8n8.x4.shared.b16 {%0,%1,%2,%3}, [%4];"
                 : "=r"(r0), "=r"(r1), "=r"(r2), "=r"(r3) : "r"(saddr));
}
__device__ __forceinline__ u32 smem_u32(const void* p) {
    u32 a; asm("{ .reg .u64 t; cvta.to.shared.u64 t, %1; cvt.u32.u64 %0, t; }" : "=r"(a) : "l"(p));
    return a;
}
__device__ __forceinline__ void split2f(float x0, float x1, u32& hi, u32& lo) {
    __half2 h = __floats2half2_rn(x0, x1);
    __half2 l = __floats2half2_rn((x0 - __low2float(h))  * LO_SCALE,
                                  (x1 - __high2float(h)) * LO_SCALE);
    hi = *(u32*)&h; lo = *(u32*)&l;
}

#define HBST 68   // shared h buffer row stride (words); h1 uses 0..31, h2 0..63
#define NST  132  // node rows: 128 words + 4 pad

// --------- precomputed fp16 B-fragments (coalesced per group L) ----------
__device__ u32 g3h[256 * 64];    // point W3: L = ((np*4+w)*2+nt)*8 + ks
__device__ u32 g2h[64 * 64];     // point W2: L = ntg*4 + ks (ntg 0..15)
__device__ u32 g_n1h[512 * 64];  // node sg_w1 hi: L = ntg*16 + ks
__device__ u32 g_n1l[512 * 64];
__device__ u32 g_n2h[512 * 64];
__device__ u32 g_n2l[512 * 64];
__device__ u32 g_seh[208 * 64];  // se_w: L = nt*16 + ks (col<100 else 0)
__device__ u32 g_sel[208 * 64];

__global__ void frag_kernel(const float* __restrict__ pw2, const float* __restrict__ pw3,
                            const float* __restrict__ n1,  const float* __restrict__ n2,
                            const float* __restrict__ sew)
{
    const int bid = blockIdx.x;
    if (bid < 64) {                      // point W3 (single fp16)
        const int gid = bid * 128 + threadIdx.x;
        const int L = gid >> 5, lane = gid & 31;
        const int ks = L & 7, nt = (L >> 3) & 1, w = (L >> 4) & 3, np = L >> 6;
        const int gcol = np * 64 + w * 16 + nt * 8 + (lane >> 2);
        const int k0 = 16 * ks + 2 * (lane & 3);
        __half2 h0 = __floats2half2_rn(pw3[(size_t)k0 * 256 + gcol],
                                       pw3[(size_t)(k0 + 1) * 256 + gcol]);
        __half2 h1 = __floats2half2_rn(pw3[(size_t)(k0 + 8) * 256 + gcol],
                                       pw3[(size_t)(k0 + 9) * 256 + gcol]);
        g3h[L * 64 + lane * 2]     = *(u32*)&h0;
        g3h[L * 64 + lane * 2 + 1] = *(u32*)&h1;
    } else if (bid < 80) {               // point W2 (single fp16)
        const int gid = (bid - 64) * 128 + threadIdx.x;
        const int L = gid >> 5, lane = gid & 31;
        const int ks = L & 3, ntg = L >> 2;
        const int gcol = ntg * 8 + (lane >> 2);
        const int k0 = 16 * ks + 2 * (lane & 3);
        __half2 h0 = __floats2half2_rn(pw2[(size_t)k0 * 128 + gcol],
                                       pw2[(size_t)(k0 + 1) * 128 + gcol]);
        __half2 h1 = __floats2half2_rn(pw2[(size_t)(k0 + 8) * 128 + gcol],
                                       pw2[(size_t)(k0 + 9) * 128 + gcol]);
        g2h[L * 64 + lane * 2]     = *(u32*)&h0;
        g2h[L * 64 + lane * 2 + 1] = *(u32*)&h1;
    } else if (bid < 336) {              // node sg_w1/sg_w2 (hi/lo)
        const int gid = (bid - 80) * 128 + threadIdx.x;
        const int sel = gid >= 16384;
        const float* w = sel ? n2 : n1;
        u32* dh = sel ? g_n2h : g_n1h;
        u32* dl = sel ? g_n2l : g_n1l;
        const int g = gid & 16383;
        const int L = g >> 5, lane = g & 31;
        const int ks = L & 15, ntg = L >> 4;
        const int col = ntg * 8 + (lane >> 2);
        const int k0 = 16 * ks + 2 * (lane & 3);
        u32 h0, l0, h1, l1;
        split2f(w[(size_t)k0 * 256 + col],       w[(size_t)(k0 + 1) * 256 + col], h0, l0);
        split2f(w[(size_t)(k0 + 8) * 256 + col], w[(size_t)(k0 + 9) * 256 + col], h1, l1);
        dh[L * 64 + lane * 2]     = h0;
        dh[L * 64 + lane * 2 + 1] = h1;
        dl[L * 64 + lane * 2]     = l0;
        dl[L * 64 + lane * 2 + 1] = l1;
    } else {                             // se_w (hi/lo)
        const int gid = (bid - 336) * 128 + threadIdx.x;
        if (gid < 6656) {
            const int L = gid >> 5, lane = gid & 31;
            const int ks = L & 15, nt = L >> 4;
            const int col = nt * 8 + (lane >> 2);
            const int k0 = 16 * ks + 2 * (lane & 3);
            const bool ok = (col < EMB);
            u32 h0, l0, h1, l1;
            split2f(ok ? sew[(size_t)k0 * EMB + col] : 0.0f,
                    ok ? sew[(size_t)(k0 + 1) * EMB + col] : 0.0f, h0, l0);
            split2f(ok ? sew[(size_t)(k0 + 8) * EMB + col] : 0.0f,
                    ok ? sew[(size_t)(k0 + 9) * EMB + col] : 0.0f, h1, l1);
            g_seh[L * 64 + lane * 2]     = h0;
            g_seh[L * 64 + lane * 2 + 1] = h1;
            g_sel[L * 64 + lane * 2]     = l0;
            g_sel[L * 64 + lane * 2 + 1] = l1;
        }
    }
}

// Dynamic smem: hbuf(128*68=8704) + feat(256) words = 35840 B
#define P_DSM_WORDS (8704 + 256)
#define P_DSM_BYTES (P_DSM_WORDS * 4)

// ---------------------------------------------------------------------------
// Point branch: block = one object, 128 threads, single pass, IN-PLACE h1/h2.
//  L1: FFMA -> h1 fp16 (words 0..31 of each row).
//  L2: row-exclusive warps (warp w owns rows 32w..32w+32, ALL cols);
//      reads h1 of its rows first, then overwrites rows with h2 (words 0..63).
//  L3: column-split warps (64 cols each), np-single B residency.
// ---------------------------------------------------------------------------
__global__ __launch_bounds__(128, 6) void point_branch_kernel(
    const float* __restrict__ pts,
    const float* __restrict__ w1, const float* __restrict__ b1,
    const float* __restrict__ b2, const float* __restrict__ b3,
    const float* __restrict__ oew, const float* __restrict__ oeb,
    float* __restrict__ out)
{
    extern __shared__ u32 dsm[];
    u32* hb = dsm;                        // 128 x HBST
    float* feat_s = (float*)(dsm + 8704);

    const u32 hb_u = smem_u32(hb);

    const int n    = blockIdx.x;
    const int t    = threadIdx.x;
    const int w_   = t >> 5;
    const int lane = t & 31;

    const int lm_row = lane & 15;
    const int lm_col = (lane >> 4) << 2;

    // ================= layer 1: all 128 points -> h1 fp16 ===================
#pragma unroll
    for (int pg = 0; pg < 4; ++pg) {
        const int pl = t & 31;
        const int j0 = (t >> 5) * 16;
        const int row = pg * 32 + pl;
        const size_t pb = ((size_t)n * PPT + row) * 3;
        const float x = pts[pb + 0], y = pts[pb + 1], z = pts[pb + 2];
        u32 hw[8];
#pragma unroll
        for (int q = 0; q < 8; ++q) {
            const int jj = j0 + 2 * q;
            float r0 = fmaf(x, __ldg(w1 + jj),     fmaf(y, __ldg(w1 + 64 + jj),     fmaf(z, __ldg(w1 + 128 + jj),     __ldg(b1 + jj))));
            float r1 = fmaf(x, __ldg(w1 + jj + 1), fmaf(y, __ldg(w1 + 64 + jj + 1), fmaf(z, __ldg(w1 + 128 + jj + 1), __ldg(b1 + jj + 1))));
            __half2 h = __floats2half2_rn(fmaxf(r0, 0.0f), fmaxf(r1, 0.0f));
            hw[q] = *(u32*)&h;
        }
        const int wb = row * HBST + (j0 >> 1);
        *(uint4*)&hb[wb]     = make_uint4(hw[0], hw[1], hw[2], hw[3]);
        *(uint4*)&hb[wb + 4] = make_uint4(hw[4], hw[5], hw[6], hw[7]);
    }
    __syncthreads();

    // ================= layer 2: row-exclusive, in-place =====================
    {
        const int mt0 = w_ * 2;
#pragma unroll
        for (int mtl = 0; mtl < 2; ++mtl) {
            const int mt = mt0 + mtl;
            u32 a[4][4];
#pragma unroll
            for (int ks = 0; ks < 4; ++ks) {
                const u32 aoff = (u32)(((mt * 16 + lm_row) * HBST + ks * 8 + lm_col) * 4);
                ldsm_x4(a[ks][0], a[ks][1], a[ks][2], a[ks][3], hb_u + aoff);
            }
            // all h1 reads for these 16 rows complete; safe to overwrite
#pragma unroll
            for (int ntg = 0; ntg < 16; ++ntg) {
                const u32 lb = (u32)((ntg * 4) * 64 + lane * 2);
                const float2 bb = __ldg((const float2*)(b2 + ntg * 8 + 2 * (lane & 3)));
                float acc[4] = { bb.x, bb.y, bb.x, bb.y };
#pragma unroll
                for (int ks = 0; ks < 4; ++ks) {
                    const uint2 b = __ldg((const uint2*)(g2h + lb + ks * 64));
                    mma_f16(acc, a[ks][0], a[ks][1], a[ks][2], a[ks][3], b.x, b.y);
                }
                const int r0 = mt * 16 + (lane >> 2);
                const int wd = ntg * 4 + (lane & 3);
                __half2 p0 = __floats2half2_rn(fmaxf(acc[0], 0.0f), fmaxf(acc[1], 0.0f));
                __half2 p1 = __floats2half2_rn(fmaxf(acc[2], 0.0f), fmaxf(acc[3], 0.0f));
                hb[r0 * HBST + wd]       = *(u32*)&p0;
                hb[(r0 + 8) * HBST + wd] = *(u32*)&p1;
            }
        }
    }
    __syncthreads();

    // ================= layer 3: column-split, np-single =====================
#pragma unroll 1
    for (int np = 0; np < 4; ++np) {
        uint2 bh[2][8];
#pragma unroll
        for (int nt = 0; nt < 2; ++nt) {
            const u32 lb = (u32)((((np * 4 + w_) * 2 + nt) * 8) * 64 + lane * 2);
#pragma unroll
            for (int ks = 0; ks < 8; ++ks)
                bh[nt][ks] = __ldg((const uint2*)(g3h + lb + ks * 64));
        }

        float rm[2][2] = { {-3.0e38f, -3.0e38f}, {-3.0e38f, -3.0e38f} };

#pragma unroll
        for (int mt = 0; mt < 8; ++mt) {
            float acc[2][4];
#pragma unroll
            for (int nt = 0; nt < 2; ++nt)
#pragma unroll
                for (int q = 0; q < 4; ++q) acc[nt][q] = 0.0f;

#pragma unroll
            for (int kh = 0; kh < 2; ++kh) {
                u32 a[4][4];
#pragma unroll
                for (int ksl = 0; ksl < 4; ++ksl) {
                    const int ks = kh * 4 + ksl;
                    const u32 aoff = (u32)(((mt * 16 + lm_row) * HBST + ks * 8 + lm_col) * 4);
                    ldsm_x4(a[ksl][0], a[ksl][1], a[ksl][2], a[ksl][3], hb_u + aoff);
                }
#pragma unroll
                for (int nt = 0; nt < 2; ++nt)
#pragma unroll
                    for (int ksl = 0; ksl < 4; ++ksl)
                        mma_f16(acc[nt], a[ksl][0], a[ksl][1], a[ksl][2], a[ksl][3],
                                bh[nt][kh * 4 + ksl].x, bh[nt][kh * 4 + ksl].y);
            }
#pragma unroll
            for (int nt = 0; nt < 2; ++nt) {
                rm[nt][0] = fmaxf(rm[nt][0], fmaxf(acc[nt][0], acc[nt][2]));
                rm[nt][1] = fmaxf(rm[nt][1], fmaxf(acc[nt][1], acc[nt][3]));
            }
        }

#pragma unroll
        for (int nt = 0; nt < 2; ++nt)
#pragma unroll
            for (int j = 0; j < 2; ++j) {
                float m = rm[nt][j];
                m = fmaxf(m, __shfl_xor_sync(0xffffffffu, m, 4));
                m = fmaxf(m, __shfl_xor_sync(0xffffffffu, m, 8));
                m = fmaxf(m, __shfl_xor_sync(0xffffffffu, m, 16));
                if (lane < 4) {
                    const int col = np * 64 + w_ * 16 + nt * 8 + 2 * lane + j;
                    feat_s[col] = m + __ldg(b3 + col);
                }
            }
    }
    __syncthreads();

    // ---- pt_out = feat @ oe_w + oe_b
    if (t < EMB) {
        float acc = __ldg(oeb + t);
#pragma unroll 4
        for (int k = 0; k < 256; k += 4) {
            const float4 f = *(const float4*)&feat_s[k];
            acc = fmaf(f.x, __ldg(oew + (size_t)(k + 0) * EMB + t), acc);
            acc = fmaf(f.y, __ldg(oew + (size_t)(k + 1) * EMB + t), acc);
            acc = fmaf(f.z, __ldg(oew + (size_t)(k + 2) * EMB + t), acc);
            acc = fmaf(f.w, __ldg(oew + (size_t)(k + 3) * EMB + t), acc);
        }
        out[(size_t)n * OUTW + EMB + t] = acc;
    }
}

// ---------------------------------------------------------------------------
// Node branch (unchanged from R12): block = 16 rows, hi/lo 3-product splits.
// ---------------------------------------------------------------------------
__device__ __forceinline__ void node_layer(
    u32 sh_u, u32 sl_u, u32* dh, u32* dl,
    const u32* __restrict__ fh, const u32* __restrict__ fl,
    const float* __restrict__ bias, int w_, int lane, bool relu_)
{
    const int lm_row = lane & 15;
    const int lm_col = (lane >> 4) << 2;

    float acc_h[8][4], acc_m[8][4];
#pragma unroll
    for (int nt = 0; nt < 8; ++nt)
#pragma unroll
        for (int q = 0; q < 4; ++q) { acc_h[nt][q] = 0.0f; acc_m[nt][q] = 0.0f; }

#pragma unroll
    for (int kc = 0; kc < 4; ++kc) {
        u32 ah[4][4], al[4][4];
#pragma unroll
        for (int ksl = 0; ksl < 4; ++ksl) {
            const u32 aoff = (u32)((lm_row * NST + (kc * 4 + ksl) * 8 + lm_col) * 4);
            ldsm_x4(ah[ksl][0], ah[ksl][1], ah[ksl][2], ah[ksl][3], sh_u + aoff);
            ldsm_x4(al[ksl][0], al[ksl][1], al[ksl][2], al[ksl][3], sl_u + aoff);
        }
#pragma unroll
        for (int nt = 0; nt < 8; ++nt) {
#pragma unroll
            for (int ksl = 0; ksl < 4; ++ksl) {
                const int L = (w_ * 8 + nt) * 16 + kc * 4 + ksl;
                const uint2 bhv = __ldg((const uint2*)(fh + L * 64 + lane * 2));
                const uint2 blv = __ldg((const uint2*)(fl + L * 64 + lane * 2));
                mma_f16(acc_h[nt], ah[ksl][0], ah[ksl][1], ah[ksl][2], ah[ksl][3], bhv.x, bhv.y);
                mma_f16(acc_m[nt], ah[ksl][0], ah[ksl][1], ah[ksl][2], ah[ksl][3], blv.x, blv.y);
                mma_f16(acc_m[nt], al[ksl][0], al[ksl][1], al[ksl][2], al[ksl][3], bhv.x, bhv.y);
            }
        }
    }
#pragma unroll
    for (int nt = 0; nt < 8; ++nt) {
        const float2 bb = __ldg((const float2*)(bias + w_ * 64 + nt * 8 + 2 * (lane & 3)));
        float c0 = acc_h[nt][0] + LO_INV * acc_m[nt][0] + bb.x;
        float c1 = acc_h[nt][1] + LO_INV * acc_m[nt][1] + bb.y;
        float c2 = acc_h[nt][2] + LO_INV * acc_m[nt][2] + bb.x;
        float c3 = acc_h[nt][3] + LO_INV * acc_m[nt][3] + bb.y;
        if (relu_) {
            c0 = fmaxf(c0, 0.0f); c1 = fmaxf(c1, 0.0f);
            c2 = fmaxf(c2, 0.0f); c3 = fmaxf(c3, 0.0f);
        }
        const int r0 = lane >> 2;
        const int wd = w_ * 32 + nt * 4 + (lane & 3);
        u32 h0, l0, h1, l1;
        split2f(c0, c1, h0, l0);
        split2f(c2, c3, h1, l1);
        dh[r0 * NST + wd]       = h0;
        dl[r0 * NST + wd]       = l0;
        dh[(r0 + 8) * NST + wd] = h1;
        dl[(r0 + 8) * NST + wd] = l1;
    }
}

__global__ __launch_bounds__(128) void node_branch_kernel(
    const float* __restrict__ srcf,
    const float* __restrict__ reff,
    const void*  __restrict__ counts_raw,
    const float* __restrict__ b1, const float* __restrict__ b2,
    const float* __restrict__ seb,
    float* __restrict__ out)
{
    __shared__ u32 xs_h[16 * NST];
    __shared__ u32 xs_l[16 * NST];
    __shared__ u32 hs_h[16 * NST];
    __shared__ u32 hs_l[16 * NST];
    __shared__ int srow[16];
    __shared__ int sflag[16];

    const u32 xsh_u = smem_u32(xs_h), xsl_u = smem_u32(xs_l);
    const u32 hsh_u = smem_u32(hs_h), hsl_u = smem_u32(hs_l);

    const int t = threadIdx.x;
    const int w_ = t >> 5, lane = t & 31;
    const long long o0 = (long long)blockIdx.x * 16;

    if (t < 16) {
        const int* c32 = (const int*)counts_raw;
        const bool is64 = (c32[1] == 0 && c32[3] == 0);
        const long long o = o0 + t;
        long long cum = 0, ssum = 0, rsum = 0, idx = 0;
        int flag = 0;
        for (int b = 0; b < NB; ++b) {
            long long sc, rc;
            if (is64) { sc = ((const long long*)counts_raw)[2 * b]; rc = ((const long long*)counts_raw)[2 * b + 1]; }
            else      { sc = c32[2 * b]; rc = c32[2 * b + 1]; }
            const long long tot = sc + rc;
            if (o < cum + tot) {
                const long long off = o - cum;
                if (off < sc) { flag = 0; idx = ssum + off; }
                else          { flag = 1; idx = rsum + (off - sc); }
                break;
            }
            cum += tot; ssum += sc; rsum += rc;
        }
        srow[t] = (int)idx; sflag[t] = flag;
    }
    __syncthreads();

    {
        const int r = t >> 3, q = t & 7;
        const float* base = sflag[r] ? reff : srcf;
        const float* rowp = base + (size_t)srow[r] * FEAT + q * 32;
        u32* dh = &xs_h[r * NST + q * 16];
        u32* dl = &xs_l[r * NST + q * 16];
#pragma unroll
        for (int i = 0; i < 8; ++i) {
            const float4 f = __ldg((const float4*)(rowp + i * 4));
            u32 h0, l0, h1, l1;
            split2f(f.x, f.y, h0, l0);
            split2f(f.z, f.w, h1, l1);
            dh[i * 2]     = h0; dh[i * 2 + 1] = h1;
            dl[i * 2]     = l0; dl[i * 2 + 1] = l1;
        }
    }
    __syncthreads();

    node_layer(xsh_u, xsl_u, hs_h, hs_l, g_n1h, g_n1l, b1, w_, lane, true);
    __syncthreads();
    node_layer(hsh_u, hsl_u, xs_h, xs_l, g_n2h, g_n2l, b2, w_, lane, false);
    __syncthreads();

    {
        const int lm_row = lane & 15;
        const int lm_col = (lane >> 4) << 2;
#pragma unroll 1
        for (int nt = w_; nt < 13; nt += 4) {
            const int cb = nt * 8 + 2 * (lane & 3);
            float acc_h[4] = {0, 0, 0, 0}, acc_m[4] = {0, 0, 0, 0};
#pragma unroll
            for (int ks = 0; ks < 16; ++ks) {
                const uint2 bhv = __ldg((const uint2*)(g_seh + (nt * 16 + ks) * 64 + lane * 2));
                const uint2 blv = __ldg((const uint2*)(g_sel + (nt * 16 + ks) * 64 + lane * 2));
                const u32 aoff = (u32)((lm_row * NST + ks * 8 + lm_col) * 4);
                u32 a0, a1, a2, a3, c0, c1, c2, c3;
                ldsm_x4(a0, a1, a2, a3, xsh_u + aoff);
                ldsm_x4(c0, c1, c2, c3, xsl_u + aoff);
                mma_f16(acc_h, a0, a1, a2, a3, bhv.x, bhv.y);
                mma_f16(acc_m, a0, a1, a2, a3, blv.x, blv.y);
                mma_f16(acc_m, c0, c1, c2, c3, bhv.x, bhv.y);
            }
            const float bb0 = (cb     < EMB) ? __ldg(seb + cb)     : 0.0f;
            const float bb1 = (cb + 1 < EMB) ? __ldg(seb + cb + 1) : 0.0f;
            const float v0 = acc_h[0] + LO_INV * acc_m[0] + bb0;
            const float v1 = acc_h[1] + LO_INV * acc_m[1] + bb1;
            const float v2 = acc_h[2] + LO_INV * acc_m[2] + bb0;
            const float v3 = acc_h[3] + LO_INV * acc_m[3] + bb1;
            const int r0 = lane >> 2;
            if (cb < EMB) {
                out[(size_t)(o0 + r0) * OUTW + cb]     = v0;
                out[(size_t)(o0 + r0 + 8) * OUTW + cb] = v2;
            }
            if (cb + 1 < EMB) {
                out[(size_t)(o0 + r0) * OUTW + cb + 1]     = v1;
                out[(size_t)(o0 + r0 + 8) * OUTW + cb + 1] = v3;
            }
        }
    }
}

extern "C" void kernel_launch(void* const* d_in, const int* in_sizes, int n_in,
                              void* d_out, int out_size)
{
    const float* pts    = (const float*)d_in[0];
    const float* srcf   = (const float*)d_in[1];
    const float* reff   = (const float*)d_in[2];
    const void*  counts = d_in[3];
    const float* sg_w1  = (const float*)d_in[6];
    const float* sg_b1  = (const float*)d_in[7];
    const float* sg_w2  = (const float*)d_in[8];
    const float* sg_b2  = (const float*)d_in[9];
    const float* se_w   = (const float*)d_in[10];
    const float* se_b   = (const float*)d_in[11];
    const float* p_w1   = (const float*)d_in[12];
    const float* p_b1   = (const float*)d_in[13];
    const float* p_w2   = (const float*)d_in[14];
    const float* p_b2   = (const float*)d_in[15];
    const float* p_w3   = (const float*)d_in[16];
    const float* p_b3   = (const float*)d_in[17];
    const float* oe_w   = (const float*)d_in[18];
    const float* oe_b   = (const float*)d_in[19];
    float* out = (float*)d_out;

    cudaFuncSetAttribute(point_branch_kernel,
                         cudaFuncAttributeMaxDynamicSharedMemorySize, P_DSM_BYTES);

    frag_kernel<<<388, 128>>>(p_w2, p_w3, sg_w1, sg_w2, se_w);
    node_branch_kernel<<<N_TOT / 16, 128>>>(srcf, reff, counts,
                                            sg_b1, sg_b2, se_b, out);
    point_branch_kernel<<<N_TOT, 128, P_DSM_BYTES>>>(pts, p_w1, p_b1, p_b2, p_b3,
                                                     oe_w, oe_b, out);
}

// round 14
// speedup vs baseline: 2.0446x; 2.0446x over previous
#include <cuda_runtime.h>
#include <cuda_fp16.h>
#include <stdint.h>

#define NB    16
#define N_TOT 16384
#define PPT   128
#define FEAT  256
#define EMB   100
#define OUTW  200

typedef unsigned long long u64;
typedef unsigned int u32;

#define LO_SCALE 2048.0f
#define LO_INV   4.8828125e-4f

// ---------------- mma / ldmatrix (portable ISA) ----------------
__device__ __forceinline__ void mma_f16(float* c,
                                        u32 a0, u32 a1, u32 a2, u32 a3,
                                        u32 b0, u32 b1) {
    asm("mma.sync.aligned.m16n8k16.row.col.f32.f16.f16.f32 "
        "{%0,%1,%2,%3}, {%4,%5,%6,%7}, {%8,%9}, {%0,%1,%2,%3};"
        : "+f"(c[0]), "+f"(c[1]), "+f"(c[2]), "+f"(c[3])
        : "r"(a0), "r"(a1), "r"(a2), "r"(a3), "r"(b0), "r"(b1));
}
__device__ __forceinline__ void ldsm_x4(u32& r0, u32& r1, u32& r2, u32& r3, u32 saddr) {
    asm volatile("ldmatrix.sync.aligned.m8n8.x4.shared.b16 {%0,%1,%2,%3}, [%4];"
                 : "=r"(r0), "=r"(r1), "=r"(r2), "=r"(r3) : "r"(saddr));
}
__device__ __forceinline__ u32 smem_u32(const void* p) {
    u32 a; asm("{ .reg .u64 t; cvta.to.shared.u64 t, %1; cvt.u32.u64 %0, t; }" : "=r"(a) : "l"(p));
    return a;
}
__device__ __forceinline__ void split2f(float x0, float x1, u32& hi, u32& lo) {
    __half2 h = __floats2half2_rn(x0, x1);
    __half2 l = __floats2half2_rn((x0 - __low2float(h))  * LO_SCALE,
                                  (x1 - __high2float(h)) * LO_SCALE);
    hi = *(u32*)&h; lo = *(u32*)&l;
}

#define H1ST 36   // point h1 rows: 32 words (fp16x2) + 4 pad
#define H2ST 68   // point h2 rows: 64 words + 4 pad
#define NST  132  // node / ptout rows: 128 words + 4 pad

#define NODE_BLOCKS (N_TOT / 16)   // 1024

// --------- precomputed fp16 B-fragments (coalesced per group L) ----------
__device__ u32 g3h[256 * 64];    // point W3: L = ((np*4+w)*2+nt)*8 + ks
__device__ u32 g2h[64 * 64];     // point W2: L = (w*4+nt)*4 + ks
__device__ u32 g_n1h[512 * 64];  // node sg_w1 hi: L = ntg*16 + ks
__device__ u32 g_n1l[512 * 64];
__device__ u32 g_n2h[512 * 64];
__device__ u32 g_n2l[512 * 64];
__device__ u32 g_seh[208 * 64];  // se_w: L = nt*16 + ks (col<100 else 0)
__device__ u32 g_sel[208 * 64];
__device__ u32 g_oeh[208 * 64];  // oe_w: same layout as se_w
__device__ u32 g_oel[208 * 64];

// point-branch feature output (fp16x2 words), consumed by ptout_kernel
__device__ u32 g_feat[N_TOT * 128];

__global__ void frag_kernel(const float* __restrict__ pw2, const float* __restrict__ pw3,
                            const float* __restrict__ n1,  const float* __restrict__ n2,
                            const float* __restrict__ sew, const float* __restrict__ oew)
{
    const int bid = blockIdx.x;
    if (bid < 64) {                      // point W3 (single fp16)
        const int gid = bid * 128 + threadIdx.x;
        const int L = gid >> 5, lane = gid & 31;
        const int ks = L & 7, nt = (L >> 3) & 1, w = (L >> 4) & 3, np = L >> 6;
        const int gcol = np * 64 + w * 16 + nt * 8 + (lane >> 2);
        const int k0 = 16 * ks + 2 * (lane & 3);
        __half2 h0 = __floats2half2_rn(pw3[(size_t)k0 * 256 + gcol],
                                       pw3[(size_t)(k0 + 1) * 256 + gcol]);
        __half2 h1 = __floats2half2_rn(pw3[(size_t)(k0 + 8) * 256 + gcol],
                                       pw3[(size_t)(k0 + 9) * 256 + gcol]);
        g3h[L * 64 + lane * 2]     = *(u32*)&h0;
        g3h[L * 64 + lane * 2 + 1] = *(u32*)&h1;
    } else if (bid < 80) {               // point W2 (single fp16)
        const int gid = (bid - 64) * 128 + threadIdx.x;
        const int L = gid >> 5, lane = gid & 31;
        const int ks = L & 3, nt = (L >> 2) & 3, w = L >> 4;
        const int gcol = w * 32 + nt * 8 + (lane >> 2);
        const int k0 = 16 * ks + 2 * (lane & 3);
        __half2 h0 = __floats2half2_rn(pw2[(size_t)k0 * 128 + gcol],
                                       pw2[(size_t)(k0 + 1) * 128 + gcol]);
        __half2 h1 = __floats2half2_rn(pw2[(size_t)(k0 + 8) * 128 + gcol],
                                       pw2[(size_t)(k0 + 9) * 128 + gcol]);
        g2h[L * 64 + lane * 2]     = *(u32*)&h0;
        g2h[L * 64 + lane * 2 + 1] = *(u32*)&h1;
    } else if (bid < 336) {              // node sg_w1/sg_w2 (hi/lo)
        const int gid = (bid - 80) * 128 + threadIdx.x;
        const int sel = gid >= 16384;
        const float* w = sel ? n2 : n1;
        u32* dh = sel ? g_n2h : g_n1h;
        u32* dl = sel ? g_n2l : g_n1l;
        const int g = gid & 16383;
        const int L = g >> 5, lane = g & 31;
        const int ks = L & 15, ntg = L >> 4;
        const int col = ntg * 8 + (lane >> 2);
        const int k0 = 16 * ks + 2 * (lane & 3);
        u32 h0, l0, h1, l1;
        split2f(w[(size_t)k0 * 256 + col],       w[(size_t)(k0 + 1) * 256 + col], h0, l0);
        split2f(w[(size_t)(k0 + 8) * 256 + col], w[(size_t)(k0 + 9) * 256 + col], h1, l1);
        dh[L * 64 + lane * 2]     = h0;
        dh[L * 64 + lane * 2 + 1] = h1;
        dl[L * 64 + lane * 2]     = l0;
        dl[L * 64 + lane * 2 + 1] = l1;
    } else {                             // se_w / oe_w (hi/lo, padded cols)
        const int gid = (bid - 336) * 128 + threadIdx.x;
        const int sel = gid >= 6656;     // 0 = se, 1 = oe
        const int g = sel ? gid - 6656 : gid;
        if (g < 6656) {
            const float* w = sel ? oew : sew;
            u32* dh = sel ? g_oeh : g_seh;
            u32* dl = sel ? g_oel : g_sel;
            const int L = g >> 5, lane = g & 31;
            const int ks = L & 15, nt = L >> 4;
            const int col = nt * 8 + (lane >> 2);
            const int k0 = 16 * ks + 2 * (lane & 3);
            const bool ok = (col < EMB);
            u32 h0, l0, h1, l1;
            split2f(ok ? w[(size_t)k0 * EMB + col] : 0.0f,
                    ok ? w[(size_t)(k0 + 1) * EMB + col] : 0.0f, h0, l0);
            split2f(ok ? w[(size_t)(k0 + 8) * EMB + col] : 0.0f,
                    ok ? w[(size_t)(k0 + 9) * EMB + col] : 0.0f, h1, l1);
            dh[L * 64 + lane * 2]     = h0;
            dh[L * 64 + lane * 2 + 1] = h1;
            dl[L * 64 + lane * 2]     = l0;
            dl[L * 64 + lane * 2 + 1] = l1;
        }
    }
}

// Dynamic smem: max(point h2+h1 = 8704+4608, node 4*2112 = 8448) = 13312 words
#define DSM_WORDS 13312
#define DSM_BYTES (DSM_WORDS * 4)

// ---------------------------------------------------------------------------
// node path helper (R12 node_layer, unchanged)
// ---------------------------------------------------------------------------
__device__ __forceinline__ void node_layer(
    u32 sh_u, u32 sl_u, u32* dh, u32* dl,
    const u32* __restrict__ fh, const u32* __restrict__ fl,
    const float* __restrict__ bias, int w_, int lane, bool relu_)
{
    const int lm_row = lane & 15;
    const int lm_col = (lane >> 4) << 2;

    float acc_h[8][4], acc_m[8][4];
#pragma unroll
    for (int nt = 0; nt < 8; ++nt)
#pragma unroll
        for (int q = 0; q < 4; ++q) { acc_h[nt][q] = 0.0f; acc_m[nt][q] = 0.0f; }

#pragma unroll
    for (int kc = 0; kc < 4; ++kc) {
        u32 ah[4][4], al[4][4];
#pragma unroll
        for (int ksl = 0; ksl < 4; ++ksl) {
            const u32 aoff = (u32)((lm_row * NST + (kc * 4 + ksl) * 8 + lm_col) * 4);
            ldsm_x4(ah[ksl][0], ah[ksl][1], ah[ksl][2], ah[ksl][3], sh_u + aoff);
            ldsm_x4(al[ksl][0], al[ksl][1], al[ksl][2], al[ksl][3], sl_u + aoff);
        }
#pragma unroll
        for (int nt = 0; nt < 8; ++nt) {
#pragma unroll
            for (int ksl = 0; ksl < 4; ++ksl) {
                const int L = (w_ * 8 + nt) * 16 + kc * 4 + ksl;
                const uint2 bhv = __ldg((const uint2*)(fh + L * 64 + lane * 2));
                const uint2 blv = __ldg((const uint2*)(fl + L * 64 + lane * 2));
                mma_f16(acc_h[nt], ah[ksl][0], ah[ksl][1], ah[ksl][2], ah[ksl][3], bhv.x, bhv.y);
                mma_f16(acc_m[nt], ah[ksl][0], ah[ksl][1], ah[ksl][2], ah[ksl][3], blv.x, blv.y);
                mma_f16(acc_m[nt], al[ksl][0], al[ksl][1], al[ksl][2], al[ksl][3], bhv.x, bhv.y);
            }
        }
    }
#pragma unroll
    for (int nt = 0; nt < 8; ++nt) {
        const float2 bb = __ldg((const float2*)(bias + w_ * 64 + nt * 8 + 2 * (lane & 3)));
        float c0 = acc_h[nt][0] + LO_INV * acc_m[nt][0] + bb.x;
        float c1 = acc_h[nt][1] + LO_INV * acc_m[nt][1] + bb.y;
        float c2 = acc_h[nt][2] + LO_INV * acc_m[nt][2] + bb.x;
        float c3 = acc_h[nt][3] + LO_INV * acc_m[nt][3] + bb.y;
        if (relu_) {
            c0 = fmaxf(c0, 0.0f); c1 = fmaxf(c1, 0.0f);
            c2 = fmaxf(c2, 0.0f); c3 = fmaxf(c3, 0.0f);
        }
        const int r0 = lane >> 2;
        const int wd = w_ * 32 + nt * 4 + (lane & 3);
        u32 h0, l0, h1, l1;
        split2f(c0, c1, h0, l0);
        split2f(c2, c3, h1, l1);
        dh[r0 * NST + wd]       = h0;
        dl[r0 * NST + wd]       = l0;
        dh[(r0 + 8) * NST + wd] = h1;
        dl[(r0 + 8) * NST + wd] = l1;
    }
}

// ---------------------------------------------------------------------------
// Fused main kernel: blocks [0, NODE_BLOCKS) = node path (16 rows each),
//                    blocks [NODE_BLOCKS, ...) = point path (1 object each).
// ---------------------------------------------------------------------------
__global__ __launch_bounds__(128, 4) void main_kernel(
    const float* __restrict__ pts,
    const float* __restrict__ srcf, const float* __restrict__ reff,
    const void*  __restrict__ counts_raw,
    const float* __restrict__ w1, const float* __restrict__ b1,
    const float* __restrict__ b2, const float* __restrict__ b3,
    const float* __restrict__ nb1, const float* __restrict__ nb2,
    const float* __restrict__ seb,
    float* __restrict__ out)
{
    extern __shared__ u32 dsm[];
    __shared__ int srow[16];
    __shared__ int sflag[16];

    const int t    = threadIdx.x;
    const int w_   = t >> 5;
    const int lane = t & 31;
    const int lm_row = lane & 15;
    const int lm_col = (lane >> 4) << 2;

    if (blockIdx.x < NODE_BLOCKS) {
        // =================== NODE PATH ======================================
        u32* xs_h = dsm;
        u32* xs_l = dsm + 2112;
        u32* hs_h = dsm + 4224;
        u32* hs_l = dsm + 6336;
        const u32 xsh_u = smem_u32(xs_h), xsl_u = smem_u32(xs_l);
        const u32 hsh_u = smem_u32(hs_h), hsl_u = smem_u32(hs_l);

        const long long o0 = (long long)blockIdx.x * 16;

        if (t < 16) {
            const int* c32 = (const int*)counts_raw;
            const bool is64 = (c32[1] == 0 && c32[3] == 0);
            const long long o = o0 + t;
            long long cum = 0, ssum = 0, rsum = 0, idx = 0;
            int flag = 0;
            for (int b = 0; b < NB; ++b) {
                long long sc, rc;
                if (is64) { sc = ((const long long*)counts_raw)[2 * b]; rc = ((const long long*)counts_raw)[2 * b + 1]; }
                else      { sc = c32[2 * b]; rc = c32[2 * b + 1]; }
                const long long tot = sc + rc;
                if (o < cum + tot) {
                    const long long off = o - cum;
                    if (off < sc) { flag = 0; idx = ssum + off; }
                    else          { flag = 1; idx = rsum + (off - sc); }
                    break;
                }
                cum += tot; ssum += sc; rsum += rc;
            }
            srow[t] = (int)idx; sflag[t] = flag;
        }
        __syncthreads();

        {
            const int r = t >> 3, q = t & 7;
            const float* base = sflag[r] ? reff : srcf;
            const float* rowp = base + (size_t)srow[r] * FEAT + q * 32;
            u32* dh = &xs_h[r * NST + q * 16];
            u32* dl = &xs_l[r * NST + q * 16];
#pragma unroll
            for (int i = 0; i < 8; ++i) {
                const float4 f = __ldg((const float4*)(rowp + i * 4));
                u32 h0, l0, h1, l1;
                split2f(f.x, f.y, h0, l0);
                split2f(f.z, f.w, h1, l1);
                dh[i * 2]     = h0; dh[i * 2 + 1] = h1;
                dl[i * 2]     = l0; dl[i * 2 + 1] = l1;
            }
        }
        __syncthreads();

        node_layer(xsh_u, xsl_u, hs_h, hs_l, g_n1h, g_n1l, nb1, w_, lane, true);
        __syncthreads();
        node_layer(hsh_u, hsl_u, xs_h, xs_l, g_n2h, g_n2l, nb2, w_, lane, false);
        __syncthreads();

#pragma unroll 1
        for (int nt = w_; nt < 13; nt += 4) {
            const int cb = nt * 8 + 2 * (lane & 3);
            float acc_h[4] = {0, 0, 0, 0}, acc_m[4] = {0, 0, 0, 0};
#pragma unroll
            for (int ks = 0; ks < 16; ++ks) {
                const uint2 bhv = __ldg((const uint2*)(g_seh + (nt * 16 + ks) * 64 + lane * 2));
                const uint2 blv = __ldg((const uint2*)(g_sel + (nt * 16 + ks) * 64 + lane * 2));
                const u32 aoff = (u32)((lm_row * NST + ks * 8 + lm_col) * 4);
                u32 a0, a1, a2, a3, c0, c1, c2, c3;
                ldsm_x4(a0, a1, a2, a3, xsh_u + aoff);
                ldsm_x4(c0, c1, c2, c3, xsl_u + aoff);
                mma_f16(acc_h, a0, a1, a2, a3, bhv.x, bhv.y);
                mma_f16(acc_m, a0, a1, a2, a3, blv.x, blv.y);
                mma_f16(acc_m, c0, c1, c2, c3, bhv.x, bhv.y);
            }
            const float bb0 = (cb     < EMB) ? __ldg(seb + cb)     : 0.0f;
            const float bb1 = (cb + 1 < EMB) ? __ldg(seb + cb + 1) : 0.0f;
            const float v0 = acc_h[0] + LO_INV * acc_m[0] + bb0;
            const float v1 = acc_h[1] + LO_INV * acc_m[1] + bb1;
            const float v2 = acc_h[2] + LO_INV * acc_m[2] + bb0;
            const float v3 = acc_h[3] + LO_INV * acc_m[3] + bb1;
            const int r0 = lane >> 2;
            if (cb < EMB) {
                out[(size_t)(o0 + r0) * OUTW + cb]     = v0;
                out[(size_t)(o0 + r0 + 8) * OUTW + cb] = v2;
            }
            if (cb + 1 < EMB) {
                out[(size_t)(o0 + r0) * OUTW + cb + 1]     = v1;
                out[(size_t)(o0 + r0 + 8) * OUTW + cb + 1] = v3;
            }
        }
        return;
    }

    // =================== POINT PATH (R12 structure) =========================
    const int n = blockIdx.x - NODE_BLOCKS;
    u32* h2s = dsm;            // 128 x H2ST
    u32* h1s = dsm + 8704;     // 128 x H1ST
    const u32 h2s_u = smem_u32(h2s);
    const u32 h1s_u = smem_u32(h1s);

    // ---- layer 1: all 128 points -> h1 fp16
#pragma unroll
    for (int pg = 0; pg < 4; ++pg) {
        const int pl = t & 31;
        const int j0 = (t >> 5) * 16;
        const int row = pg * 32 + pl;
        const size_t pb = ((size_t)n * PPT + row) * 3;
        const float x = pts[pb + 0], y = pts[pb + 1], z = pts[pb + 2];
        u32 hw[8];
#pragma unroll
        for (int q = 0; q < 8; ++q) {
            const int jj = j0 + 2 * q;
            float r0 = fmaf(x, __ldg(w1 + jj),     fmaf(y, __ldg(w1 + 64 + jj),     fmaf(z, __ldg(w1 + 128 + jj),     __ldg(b1 + jj))));
            float r1 = fmaf(x, __ldg(w1 + jj + 1), fmaf(y, __ldg(w1 + 64 + jj + 1), fmaf(z, __ldg(w1 + 128 + jj + 1), __ldg(b1 + jj + 1))));
            __half2 h = __floats2half2_rn(fmaxf(r0, 0.0f), fmaxf(r1, 0.0f));
            hw[q] = *(u32*)&h;
        }
        const int wb = row * H1ST + (j0 >> 1);
        *(uint4*)&h1s[wb]     = make_uint4(hw[0], hw[1], hw[2], hw[3]);
        *(uint4*)&h1s[wb + 4] = make_uint4(hw[4], hw[5], hw[6], hw[7]);
    }
    __syncthreads();

    // ---- layer 2: fp16 mma, column-split, mt 0..8
    {
        uint2 bh[4][4];
        float2 bb[4];
#pragma unroll
        for (int nt = 0; nt < 4; ++nt) {
            const u32 lb = (u32)(((w_ * 4 + nt) * 4) * 64 + lane * 2);
#pragma unroll
            for (int ks = 0; ks < 4; ++ks)
                bh[nt][ks] = __ldg((const uint2*)(g2h + lb + ks * 64));
            bb[nt] = __ldg((const float2*)(b2 + w_ * 32 + nt * 8 + 2 * (lane & 3)));
        }

#pragma unroll
        for (int mt = 0; mt < 8; ++mt) {
            u32 a[4][4];
#pragma unroll
            for (int ks = 0; ks < 4; ++ks) {
                const u32 aoff = (u32)(((mt * 16 + lm_row) * H1ST + ks * 8 + lm_col) * 4);
                ldsm_x4(a[ks][0], a[ks][1], a[ks][2], a[ks][3], h1s_u + aoff);
            }
#pragma unroll
            for (int nt = 0; nt < 4; ++nt) {
                float acc[4] = { bb[nt].x, bb[nt].y, bb[nt].x, bb[nt].y };
#pragma unroll
                for (int ks = 0; ks < 4; ++ks)
                    mma_f16(acc, a[ks][0], a[ks][1], a[ks][2], a[ks][3],
                            bh[nt][ks].x, bh[nt][ks].y);
                const int r0 = mt * 16 + (lane >> 2);
                const int wd = w_ * 16 + nt * 4 + (lane & 3);
                __half2 p0 = __floats2half2_rn(fmaxf(acc[0], 0.0f), fmaxf(acc[1], 0.0f));
                __half2 p1 = __floats2half2_rn(fmaxf(acc[2], 0.0f), fmaxf(acc[3], 0.0f));
                h2s[r0 * H2ST + wd]       = *(u32*)&p0;
                h2s[(r0 + 8) * H2ST + wd] = *(u32*)&p1;
            }
        }
    }
    __syncthreads();

    // ---- layer 3: fp16 mma, np pairs; reduce -> g_feat (fp16x2)
#pragma unroll 1
    for (int npg = 0; npg < 2; ++npg) {
        uint2 bh[2][2][8];
#pragma unroll
        for (int p = 0; p < 2; ++p)
#pragma unroll
            for (int nt = 0; nt < 2; ++nt) {
                const int np = npg * 2 + p;
                const u32 lb = (u32)((((np * 4 + w_) * 2 + nt) * 8) * 64 + lane * 2);
#pragma unroll
                for (int ks = 0; ks < 8; ++ks)
                    bh[p][nt][ks] = __ldg((const uint2*)(g3h + lb + ks * 64));
            }

        float rm[2][2][2];
#pragma unroll
        for (int p = 0; p < 2; ++p)
#pragma unroll
            for (int nt = 0; nt < 2; ++nt) {
                rm[p][nt][0] = -3.0e38f; rm[p][nt][1] = -3.0e38f;
            }

#pragma unroll
        for (int mt = 0; mt < 8; ++mt) {
            u32 a[8][4];
#pragma unroll
            for (int ks = 0; ks < 8; ++ks) {
                const u32 aoff = (u32)(((mt * 16 + lm_row) * H2ST + ks * 8 + lm_col) * 4);
                ldsm_x4(a[ks][0], a[ks][1], a[ks][2], a[ks][3], h2s_u + aoff);
            }
#pragma unroll
            for (int p = 0; p < 2; ++p)
#pragma unroll
                for (int nt = 0; nt < 2; ++nt) {
                    float acc[4] = { 0.0f, 0.0f, 0.0f, 0.0f };
#pragma unroll
                    for (int ks = 0; ks < 8; ++ks)
                        mma_f16(acc, a[ks][0], a[ks][1], a[ks][2], a[ks][3],
                                bh[p][nt][ks].x, bh[p][nt][ks].y);
                    rm[p][nt][0] = fmaxf(rm[p][nt][0], fmaxf(acc[0], acc[2]));
                    rm[p][nt][1] = fmaxf(rm[p][nt][1], fmaxf(acc[1], acc[3]));
                }
        }

#pragma unroll
        for (int p = 0; p < 2; ++p)
#pragma unroll
            for (int nt = 0; nt < 2; ++nt) {
                float m01[2];
#pragma unroll
                for (int j = 0; j < 2; ++j) {
                    float m = rm[p][nt][j];
                    m = fmaxf(m, __shfl_xor_sync(0xffffffffu, m, 4));
                    m = fmaxf(m, __shfl_xor_sync(0xffffffffu, m, 8));
                    m = fmaxf(m, __shfl_xor_sync(0xffffffffu, m, 16));
                    m01[j] = m;
                }
                if (lane < 4) {
                    const int col0 = (npg * 2 + p) * 64 + w_ * 16 + nt * 8 + 2 * lane;
                    __half2 hm = __floats2half2_rn(m01[0] + __ldg(b3 + col0),
                                                   m01[1] + __ldg(b3 + col0 + 1));
                    g_feat[(size_t)n * 128 + (col0 >> 1)] = *(u32*)&hm;
                }
            }
    }
}

// ---------------------------------------------------------------------------
// pt_out GEMM: g_feat(16384x256 fp16) @ oe_w(256x100, hi/lo frags) + oe_b.
// Block = 64 rows, 128 threads.
// ---------------------------------------------------------------------------
__global__ __launch_bounds__(128) void ptout_kernel(
    const float* __restrict__ oeb, float* __restrict__ out)
{
    __shared__ u32 xs[64 * NST];
    const u32 xs_u = smem_u32(xs);

    const int t = threadIdx.x;
    const int w_ = t >> 5, lane = t & 31;
    const int lm_row = lane & 15;
    const int lm_col = (lane >> 4) << 2;
    const long long r0g = (long long)blockIdx.x * 64;

    // load 64 rows x 128 words of feat
    {
        const int row = t >> 1, q = t & 1;
        const u32* src = g_feat + (size_t)(r0g + row) * 128 + q * 64;
        u32* dst = &xs[row * NST + q * 64];
#pragma unroll
        for (int i = 0; i < 16; ++i)
            *(uint4*)&dst[i * 4] = __ldg((const uint4*)&src[i * 4]);
    }
    __syncthreads();

#pragma unroll 1
    for (int nt = w_; nt < 13; nt += 4) {
        const int cb = nt * 8 + 2 * (lane & 3);
        float acc_h[4][4], acc_m[4][4];
#pragma unroll
        for (int mt = 0; mt < 4; ++mt)
#pragma unroll
            for (int q = 0; q < 4; ++q) { acc_h[mt][q] = 0.0f; acc_m[mt][q] = 0.0f; }

#pragma unroll
        for (int ks = 0; ks < 16; ++ks) {
            const uint2 bhv = __ldg((const uint2*)(g_oeh + (nt * 16 + ks) * 64 + lane * 2));
            const uint2 blv = __ldg((const uint2*)(g_oel + (nt * 16 + ks) * 64 + lane * 2));
#pragma unroll
            for (int mt = 0; mt < 4; ++mt) {
                const u32 aoff = (u32)(((mt * 16 + lm_row) * NST + ks * 8 + lm_col) * 4);
                u32 a0, a1, a2, a3;
                ldsm_x4(a0, a1, a2, a3, xs_u + aoff);
                mma_f16(acc_h[mt], a0, a1, a2, a3, bhv.x, bhv.y);
                mma_f16(acc_m[mt], a0, a1, a2, a3, blv.x, blv.y);
            }
        }
        const float bb0 = (cb     < EMB) ? __ldg(oeb + cb)     : 0.0f;
        const float bb1 = (cb + 1 < EMB) ? __ldg(oeb + cb + 1) : 0.0f;
#pragma unroll
        for (int mt = 0; mt < 4; ++mt) {
            const long long r = r0g + mt * 16 + (lane >> 2);
            const float v0 = acc_h[mt][0] + LO_INV * acc_m[mt][0] + bb0;
            const float v1 = acc_h[mt][1] + LO_INV * acc_m[mt][1] + bb1;
            const float v2 = acc_h[mt][2] + LO_INV * acc_m[mt][2] + bb0;
            const float v3 = acc_h[mt][3] + LO_INV * acc_m[mt][3] + bb1;
            if (cb < EMB) {
                out[(size_t)r * OUTW + EMB + cb]       = v0;
                out[(size_t)(r + 8) * OUTW + EMB + cb] = v2;
            }
            if (cb + 1 < EMB) {
                out[(size_t)r * OUTW + EMB + cb + 1]       = v1;
                out[(size_t)(r + 8) * OUTW + EMB + cb + 1] = v3;
            }
        }
    }
}

extern "C" void kernel_launch(void* const* d_in, const int* in_sizes, int n_in,
                              void* d_out, int out_size)
{
    const float* pts    = (const float*)d_in[0];
    const float* srcf   = (const float*)d_in[1];
    const float* reff   = (const float*)d_in[2];
    const void*  counts = d_in[3];
    const float* sg_w1  = (const float*)d_in[6];
    const float* sg_b1  = (const float*)d_in[7];
    const float* sg_w2  = (const float*)d_in[8];
    const float* sg_b2  = (const float*)d_in[9];
    const float* se_w   = (const float*)d_in[10];
    const float* se_b   = (const float*)d_in[11];
    const float* p_w1   = (const float*)d_in[12];
    const float* p_b1   = (const float*)d_in[13];
    const float* p_w2   = (const float*)d_in[14];
    const float* p_b2   = (const float*)d_in[15];
    const float* p_w3   = (const float*)d_in[16];
    const float* p_b3   = (const float*)d_in[17];
    const float* oe_w   = (const float*)d_in[18];
    const float* oe_b   = (const float*)d_in[19];
    float* out = (float*)d_out;

    cudaFuncSetAttribute(main_kernel,
                         cudaFuncAttributeMaxDynamicSharedMemorySize, DSM_BYTES);

    frag_kernel<<<440, 128>>>(p_w2, p_w3, sg_w1, sg_w2, se_w, oe_w);
    main_kernel<<<NODE_BLOCKS + N_TOT, 128, DSM_BYTES>>>(
        pts, srcf, reff, counts, p_w1, p_b1, p_b2, p_b3,
        sg_b1, sg_b2, se_b, out);
    ptout_kernel<<<N_TOT / 64, 128>>>(oe_b, out);
}